// round 4
// baseline (speedup 1.0000x reference)
#include <cuda_runtime.h>

// Problem shape (fixed by the dataset): B=256, N=65536.
// in:  I1, I2 as (B, N, 2) fp32 interleaved complex
// out: (B, 2N) fp32 where out[b, 0..N) = real[b,:], out[b, N..2N) = imag[b,:]
//
// R3 measured 52.16us / 85.1% DRAM with 16384 one-shot CTAs (13.84 waves).
// Single delta this round: persistent grid-stride at exactly 148*8 = 1184
// CTAs (one full wave at occupancy 8) to remove wave-quantization tail.

static constexpr int B_DIM = 256;
static constexpr int N_DIM = 65536;          // power of two -> shift/mask decode
static constexpr int N_SHIFT = 16;           // log2(N_DIM)
static constexpr unsigned N_MASK = N_DIM - 1;

static constexpr int THREADS = 256;
static constexpr int BLOCKS  = 148 * 8;      // one full wave @ occ 8
static constexpr long long TOTAL_WORK = (long long)B_DIM * N_DIM / 4; // threads' worth

__global__ void __launch_bounds__(THREADS, 8)
prod_cmp_kernel(const float4* __restrict__ in1,
                const float4* __restrict__ in2,
                float4* __restrict__ out)
{
    const long long stride = (long long)gridDim.x * blockDim.x;

    for (long long tid = (long long)blockIdx.x * blockDim.x + threadIdx.x;
         tid < TOTAL_WORK; tid += stride)
    {
        const long long cbase = tid * 4;                 // first complex index
        const unsigned b = (unsigned)(cbase >> N_SHIFT); // batch
        const unsigned k = (unsigned)(cbase & N_MASK);   // pos within row (mult of 4)

        const long long fin = cbase >> 1;                // float4 index = tid*2
        const float4 a0 = in1[fin];
        const float4 a1 = in1[fin + 1];
        const float4 b0 = in2[fin];
        const float4 b1 = in2[fin + 1];

        float4 re, im;
        re.x = fmaf(a0.x, b0.x, -a0.y * b0.y);
        im.x = fmaf(a0.y, b0.x,  a0.x * b0.y);
        re.y = fmaf(a0.z, b0.z, -a0.w * b0.w);
        im.y = fmaf(a0.w, b0.z,  a0.z * b0.w);
        re.z = fmaf(a1.x, b1.x, -a1.y * b1.y);
        im.z = fmaf(a1.y, b1.x,  a1.x * b1.y);
        re.w = fmaf(a1.z, b1.z, -a1.w * b1.w);
        im.w = fmaf(a1.w, b1.z,  a1.z * b1.w);

        const long long row_f4 = (long long)b * ((2 * N_DIM) / 4);
        __stcs(&out[row_f4 + (k >> 2)], re);
        __stcs(&out[row_f4 + (N_DIM >> 2) + (k >> 2)], im);
    }
}

extern "C" void kernel_launch(void* const* d_in, const int* in_sizes, int n_in,
                              void* d_out, int out_size)
{
    const float4* in1 = (const float4*)d_in[0];
    const float4* in2 = (const float4*)d_in[1];
    float4* out = (float4*)d_out;

    prod_cmp_kernel<<<BLOCKS, THREADS>>>(in1, in2, out);
}

// round 5
// speedup vs baseline: 1.0965x; 1.0965x over previous
#include <cuda_runtime.h>

// Problem shape (fixed by the dataset): B=256, N=65536.
// in:  I1, I2 as (B, N, 2) fp32 interleaved complex
// out: (B, 2N) fp32 where out[b, 0..N) = real[b,:], out[b, N..2N) = imag[b,:]
//
// Best config: R3 — one-shot grid 16384x256, 4 complex/thread, plain loads,
// __stcs stores: 52.16us / 85.1% DRAM. This round's single delta: 32-byte
// aggregate loads (alignas(32)) to allow LDG.256 on sm_103a; falls back to
// the identical 2x LDG.128 if ptxas declines.

static constexpr int B_DIM = 256;
static constexpr int N_DIM = 65536;          // power of two -> shift/mask decode
static constexpr int N_SHIFT = 16;           // log2(N_DIM)
static constexpr unsigned N_MASK = N_DIM - 1;

struct alignas(32) Float8 { float4 lo, hi; };

__global__ void __launch_bounds__(256, 8)
prod_cmp_kernel(const Float8* __restrict__ in1,
                const Float8* __restrict__ in2,
                float4* __restrict__ out)
{
    // Each thread handles 4 complex elements = one 32B load per input,
    // 1 float4 real store + 1 float4 imag store.
    const long long tid = (long long)blockIdx.x * blockDim.x + threadIdx.x;
    const long long cbase = tid * 4;                 // first complex index

    const unsigned b = (unsigned)(cbase >> N_SHIFT); // batch
    const unsigned k = (unsigned)(cbase & N_MASK);   // pos within row (mult of 4)

    const Float8 A = in1[tid];
    const Float8 C = in2[tid];
    const float4 a0 = A.lo, a1 = A.hi;
    const float4 b0 = C.lo, b1 = C.hi;

    float4 re, im;
    re.x = fmaf(a0.x, b0.x, -a0.y * b0.y);
    im.x = fmaf(a0.y, b0.x,  a0.x * b0.y);
    re.y = fmaf(a0.z, b0.z, -a0.w * b0.w);
    im.y = fmaf(a0.w, b0.z,  a0.z * b0.w);
    re.z = fmaf(a1.x, b1.x, -a1.y * b1.y);
    im.z = fmaf(a1.y, b1.x,  a1.x * b1.y);
    re.w = fmaf(a1.z, b1.z, -a1.w * b1.w);
    im.w = fmaf(a1.w, b1.z,  a1.z * b1.w);

    // Output row b has 2N floats: reals at [b*2N + k], imags at [b*2N + N + k].
    const long long row_f4 = (long long)b * ((2 * N_DIM) / 4);
    __stcs(&out[row_f4 + (k >> 2)], re);
    __stcs(&out[row_f4 + (N_DIM >> 2) + (k >> 2)], im);
}

extern "C" void kernel_launch(void* const* d_in, const int* in_sizes, int n_in,
                              void* d_out, int out_size)
{
    const Float8* in1 = (const Float8*)d_in[0];
    const Float8* in2 = (const Float8*)d_in[1];
    float4* out = (float4*)d_out;

    // total complex elements = B*N = 16,777,216; 4 per thread
    const long long total_threads = (long long)B_DIM * N_DIM / 4; // 4,194,304
    const int threads = 256;
    const int blocks = (int)(total_threads / threads);            // 16384

    prod_cmp_kernel<<<blocks, threads>>>(in1, in2, out);
}